// round 9
// baseline (speedup 1.0000x reference)
#include <cuda_runtime.h>
#include <math.h>
#include <stdint.h>

// QKVAttentionLegacy: qkv (4, 3072, 1024) fp32 -> out (4, 1024, 1024) fp32
// 64 heads, ch=64, T=1024. Flash attention, tf32 mma.sync.m16n8k8.
// R8: pre-kernel repacks K/V to tf32-RNA pair-packed tiles in __device__ scratch.
//     Main kernel: B-fragments = single LDS.64, zero cvt in the mainloop.
//     Q fragments persistent in registers; K/V double-buffered via cp.async.

#define SEQ   1024
#define BQ    128
#define BK    64
#define NBLK  (SEQ / BK)

#define PT 72    // smem pitch for packed K/V tiles: PT%32==8 -> LDS.64 conflict-free
#define PP 68    // P tile pitch (%32==4): GEMM2 A lanes conflict-free

// float offsets in dynamic smem
#define OFF_K0 0
#define OFF_K1 (64 * PT)
#define OFF_V0 (2 * 64 * PT)
#define OFF_V1 (3 * 64 * PT)
#define OFF_P  (4 * 64 * PT)
#define SMEM_FLOATS (OFF_P + 128 * PP)   // 27136 floats = 108544 B

// 0.125 * log2(e): whole score scale folded into Q
#define SC 0.18033688011112042f

// tf32-RNA pre-packed K/V: [head][kb][row 64][packed 64], 16KB per tile
__device__ float g_Kp[64 * 16 * 4096];
__device__ float g_Vp[64 * 16 * 4096];

__device__ __forceinline__ uint32_t f2tf32(float x) {
    uint32_t u;
    asm("cvt.rna.tf32.f32 %0, %1;" : "=r"(u) : "f"(x));
    return u;
}
__device__ __forceinline__ float ex2(float x) {
    float r;
    asm("ex2.approx.ftz.f32 %0, %1;" : "=f"(r) : "f"(x));
    return r;
}
__device__ __forceinline__ void mma_tf32(float* d,
    uint32_t a0, uint32_t a1, uint32_t a2, uint32_t a3,
    uint32_t b0, uint32_t b1)
{
    asm volatile(
        "mma.sync.aligned.m16n8k8.row.col.f32.tf32.tf32.f32 "
        "{%0,%1,%2,%3}, {%4,%5,%6,%7}, {%8,%9}, {%0,%1,%2,%3};"
        : "+f"(d[0]), "+f"(d[1]), "+f"(d[2]), "+f"(d[3])
        : "r"(a0), "r"(a1), "r"(a2), "r"(a3), "r"(b0), "r"(b1));
}
__device__ __forceinline__ void cp16(uint32_t saddr, const void* gptr) {
    asm volatile("cp.async.cg.shared.global [%0], [%1], 16;"
                 :: "r"(saddr), "l"(gptr));
}
// packed index -> source index: pc = 8a + 2t + h  <->  idx = 8a + t + 4h
__device__ __forceinline__ int unpk(int pc) {
    return 8 * (pc >> 3) + ((pc & 7) >> 1) + 4 * (pc & 1);
}

// ---------------- pre-kernel: repack K,V to tf32 pair-packed tiles ----------
__global__ void __launch_bounds__(128)
repack_kernel(const float* __restrict__ qkv)
{
    __shared__ float stage[64][68];
    const int tile = blockIdx.x;          // 0..1023 = head*16 + kb
    const int head = tile >> 4, kb = tile & 15;
    const int tid  = threadIdx.x;
    const float* base = qkv + (size_t)head * 192 * 1024 + kb * 64;
    const float* Kg = base +  64 * 1024;
    const float* Vg = base + 128 * 1024;
    float* outK = g_Kp + tile * 4096;
    float* outV = g_Vp + tile * 4096;

    // ---- K: stage[c][k] then write transposed+packed out[k][pc(c)] ----
    for (int i = tid; i < 64 * 16; i += 128) {
        int c = i >> 4, q = i & 15;
        *(float4*)(&stage[c][q * 4]) = *(const float4*)(Kg + c * 1024 + q * 4);
    }
    __syncthreads();
    for (int i = tid; i < 64 * 16; i += 128) {
        int k = i >> 4, j = i & 15;
        float4 w;
        w.x = __uint_as_float(f2tf32(stage[unpk(4 * j + 0)][k]));
        w.y = __uint_as_float(f2tf32(stage[unpk(4 * j + 1)][k]));
        w.z = __uint_as_float(f2tf32(stage[unpk(4 * j + 2)][k]));
        w.w = __uint_as_float(f2tf32(stage[unpk(4 * j + 3)][k]));
        *(float4*)(outK + k * 64 + 4 * j) = w;
    }
    __syncthreads();

    // ---- V: stage[c][s] then write row-permuted out[c][pc(s)] ----
    for (int i = tid; i < 64 * 16; i += 128) {
        int c = i >> 4, q = i & 15;
        *(float4*)(&stage[c][q * 4]) = *(const float4*)(Vg + c * 1024 + q * 4);
    }
    __syncthreads();
    for (int i = tid; i < 64 * 16; i += 128) {
        int c = i >> 4, j = i & 15;
        float4 w;
        w.x = __uint_as_float(f2tf32(stage[c][unpk(4 * j + 0)]));
        w.y = __uint_as_float(f2tf32(stage[c][unpk(4 * j + 1)]));
        w.z = __uint_as_float(f2tf32(stage[c][unpk(4 * j + 2)]));
        w.w = __uint_as_float(f2tf32(stage[c][unpk(4 * j + 3)]));
        *(float4*)(outV + c * 64 + 4 * j) = w;
    }
}

// ---------------- main attention kernel ----------------
__global__ void __launch_bounds__(128, 2)
attn_tf32_kernel(const float* __restrict__ qkv, float* __restrict__ out)
{
    extern __shared__ float smem[];
    float* Ps = smem + OFF_P;

    const int head  = blockIdx.y;        // 0..63
    const int qtile = blockIdx.x;        // 0..7
    const int tid   = threadIdx.x;       // 0..127
    const int lane  = tid & 31;
    const int wid   = tid >> 5;          // 0..3
    const int g     = lane >> 2;         // 0..7
    const int tig   = lane & 3;          // 0..3
    const int qb    = wid * 32;          // warp's q-row base (two m16 tiles)

    const float* Qg = qkv + (size_t)head * 192 * 1024;
    const float* Kt = g_Kp + (size_t)head * 16 * 4096;
    const float* Vt = g_Vp + (size_t)head * 16 * 4096;
    const int q0 = qtile * BQ;

    const uint32_t smem_u32 = (uint32_t)__cvta_generic_to_shared(smem);
    const uint32_t ku32[2] = { smem_u32 + OFF_K0 * 4u, smem_u32 + OFF_K1 * 4u };
    const uint32_t vu32[2] = { smem_u32 + OFF_V0 * 4u, smem_u32 + OFF_V1 * 4u };

    // ---- issue cp.async for K/V block 0 (contiguous 16KB tiles) ----
    {
        #pragma unroll
        for (int j = 0; j < 8; j++) {
            int i = tid + 128 * j, r = i >> 4, q = i & 15;
            cp16(ku32[0] + (r * PT + q * 4) * 4u, Kt + r * 64 + q * 4);
            cp16(vu32[0] + (r * PT + q * 4) * 4u, Vt + r * 64 + q * 4);
        }
        asm volatile("cp.async.commit_group;");
    }

    // ---- Q fragments, loop-invariant (scaled by SC, tf32 RNA) ----
    uint32_t qA[8][2][4];
    {
        const float* qc = Qg + q0 + qb + g;
        #pragma unroll
        for (int s = 0; s < 8; s++) {
            int c0 = 8 * s + tig;
            #pragma unroll
            for (int mm = 0; mm < 2; mm++) {
                int col = 16 * mm;
                qA[s][mm][0] = f2tf32(qc[(size_t)c0 * 1024 + col] * SC);
                qA[s][mm][1] = f2tf32(qc[(size_t)c0 * 1024 + col + 8] * SC);
                qA[s][mm][2] = f2tf32(qc[(size_t)(c0 + 4) * 1024 + col] * SC);
                qA[s][mm][3] = f2tf32(qc[(size_t)(c0 + 4) * 1024 + col + 8] * SC);
            }
        }
    }

    float o[2][8][4];
    #pragma unroll
    for (int mm = 0; mm < 2; mm++)
        #pragma unroll
        for (int n = 0; n < 8; n++)
            { o[mm][n][0]=0.f; o[mm][n][1]=0.f; o[mm][n][2]=0.f; o[mm][n][3]=0.f; }
    float m_i[2][2] = {{-INFINITY,-INFINITY},{-INFINITY,-INFINITY}};
    float l_i[2][2] = {{0.f,0.f},{0.f,0.f}};

    for (int kb = 0; kb < NBLK; kb++) {
        const int b = kb & 1;
        const float* ksb = smem + (b ? OFF_K1 : OFF_K0);
        const float* vsb = smem + (b ? OFF_V1 : OFF_V0);

        __syncthreads();    // all warps done reading buf b^1

        if (kb + 1 < NBLK) {
            const float* Kn = Kt + (kb + 1) * 4096;
            const float* Vn = Vt + (kb + 1) * 4096;
            #pragma unroll
            for (int j = 0; j < 8; j++) {
                int i = tid + 128 * j, r = i >> 4, q = i & 15;
                cp16(ku32[b ^ 1] + (r * PT + q * 4) * 4u, Kn + r * 64 + q * 4);
                cp16(vu32[b ^ 1] + (r * PT + q * 4) * 4u, Vn + r * 64 + q * 4);
            }
        }
        asm volatile("cp.async.commit_group;");
        asm volatile("cp.async.wait_group 1;");
        __syncthreads();

        // ---- GEMM1: z = Q^T K  (B-fragments: one LDS.64, no cvt) ----
        float z[2][8][4];
        #pragma unroll
        for (int mm = 0; mm < 2; mm++)
            #pragma unroll
            for (int n = 0; n < 8; n++)
                { z[mm][n][0]=0.f; z[mm][n][1]=0.f; z[mm][n][2]=0.f; z[mm][n][3]=0.f; }
        #pragma unroll
        for (int s = 0; s < 8; s++) {
            const float* kr = ksb + g * PT + 8 * s + 2 * tig;
            #pragma unroll
            for (int n = 0; n < 8; n++) {
                float2 bb = *(const float2*)(kr + n * 8 * PT);
                uint32_t b0 = __float_as_uint(bb.x);
                uint32_t b1 = __float_as_uint(bb.y);
                mma_tf32(z[0][n], qA[s][0][0], qA[s][0][1], qA[s][0][2], qA[s][0][3], b0, b1);
                mma_tf32(z[1][n], qA[s][1][0], qA[s][1][1], qA[s][1][2], qA[s][1][3], b0, b1);
            }
        }

        // ---- online softmax per m-tile ----
        float corr[2][2];
        #pragma unroll
        for (int mm = 0; mm < 2; mm++) {
            float mx0 = -INFINITY, mx1 = -INFINITY;
            #pragma unroll
            for (int n = 0; n < 8; n++) {
                mx0 = fmaxf(mx0, fmaxf(z[mm][n][0], z[mm][n][1]));
                mx1 = fmaxf(mx1, fmaxf(z[mm][n][2], z[mm][n][3]));
            }
            mx0 = fmaxf(mx0, __shfl_xor_sync(0xffffffffu, mx0, 1));
            mx0 = fmaxf(mx0, __shfl_xor_sync(0xffffffffu, mx0, 2));
            mx1 = fmaxf(mx1, __shfl_xor_sync(0xffffffffu, mx1, 1));
            mx1 = fmaxf(mx1, __shfl_xor_sync(0xffffffffu, mx1, 2));

            float m0n = fmaxf(m_i[mm][0], mx0);
            float m1n = fmaxf(m_i[mm][1], mx1);
            corr[mm][0] = ex2(m_i[mm][0] - m0n);   // 0 on first block
            corr[mm][1] = ex2(m_i[mm][1] - m1n);
            m_i[mm][0] = m0n; m_i[mm][1] = m1n;

            float rs0 = 0.f, rs1 = 0.f;
            #pragma unroll
            for (int n = 0; n < 8; n++) {
                z[mm][n][0] = ex2(z[mm][n][0] - m0n);
                z[mm][n][1] = ex2(z[mm][n][1] - m0n);
                z[mm][n][2] = ex2(z[mm][n][2] - m1n);
                z[mm][n][3] = ex2(z[mm][n][3] - m1n);
                rs0 += z[mm][n][0] + z[mm][n][1];
                rs1 += z[mm][n][2] + z[mm][n][3];
            }
            rs0 += __shfl_xor_sync(0xffffffffu, rs0, 1);
            rs0 += __shfl_xor_sync(0xffffffffu, rs0, 2);
            rs1 += __shfl_xor_sync(0xffffffffu, rs1, 1);
            rs1 += __shfl_xor_sync(0xffffffffu, rs1, 2);
            l_i[mm][0] = l_i[mm][0] * corr[mm][0] + rs0;
            l_i[mm][1] = l_i[mm][1] * corr[mm][1] + rs1;
        }

        // ---- store P (tf32) to warp-private rows; rescale o ----
        #pragma unroll
        for (int mm = 0; mm < 2; mm++) {
            float* prow = Ps + (qb + 16 * mm + g) * PP + 2 * tig;
            #pragma unroll
            for (int n = 0; n < 8; n++) {
                o[mm][n][0] *= corr[mm][0]; o[mm][n][1] *= corr[mm][0];
                o[mm][n][2] *= corr[mm][1]; o[mm][n][3] *= corr[mm][1];
                uint32_t p0 = f2tf32(z[mm][n][0]), p1 = f2tf32(z[mm][n][1]);
                uint32_t p2 = f2tf32(z[mm][n][2]), p3 = f2tf32(z[mm][n][3]);
                asm volatile("st.shared.v2.b32 [%0], {%1,%2};"
                    :: "l"(__cvta_generic_to_shared(prow + 8 * n)), "r"(p0), "r"(p1));
                asm volatile("st.shared.v2.b32 [%0], {%1,%2};"
                    :: "l"(__cvta_generic_to_shared(prow + 8 * PP + 8 * n)), "r"(p2), "r"(p3));
            }
        }
        __syncwarp();

        // ---- GEMM2: o += P V^T  (B-fragments: one LDS.64, no cvt) ----
        #pragma unroll
        for (int st = 0; st < 8; st++) {
            const float* pa0 = Ps + (qb + g) * PP + 8 * st + tig;
            const float* pa1 = pa0 + 16 * PP;
            uint32_t a00 = __float_as_uint(pa0[0]);
            uint32_t a01 = __float_as_uint(pa0[8 * PP]);
            uint32_t a02 = __float_as_uint(pa0[4]);
            uint32_t a03 = __float_as_uint(pa0[8 * PP + 4]);
            uint32_t a10 = __float_as_uint(pa1[0]);
            uint32_t a11 = __float_as_uint(pa1[8 * PP]);
            uint32_t a12 = __float_as_uint(pa1[4]);
            uint32_t a13 = __float_as_uint(pa1[8 * PP + 4]);
            const float* vr = vsb + g * PT + 8 * st + 2 * tig;
            #pragma unroll
            for (int n = 0; n < 8; n++) {
                float2 bb = *(const float2*)(vr + n * 8 * PT);
                uint32_t b0 = __float_as_uint(bb.x);
                uint32_t b1 = __float_as_uint(bb.y);
                mma_tf32(o[0][n], a00, a01, a02, a03, b0, b1);
                mma_tf32(o[1][n], a10, a11, a12, a13, b0, b1);
            }
        }
    }

    // ---- normalize + store: out[head*65536 + c*1024 + t_global] ----
    #pragma unroll
    for (int mm = 0; mm < 2; mm++) {
        float inv0 = 1.0f / l_i[mm][0];
        float inv1 = 1.0f / l_i[mm][1];
        float* ob = out + (size_t)head * 65536 + q0 + qb + 16 * mm + g;
        #pragma unroll
        for (int n = 0; n < 8; n++) {
            int col = 8 * n + 2 * tig;
            ob[(size_t)col * 1024]           = o[mm][n][0] * inv0;
            ob[(size_t)(col + 1) * 1024]     = o[mm][n][1] * inv0;
            ob[(size_t)col * 1024 + 8]       = o[mm][n][2] * inv1;
            ob[(size_t)(col + 1) * 1024 + 8] = o[mm][n][3] * inv1;
        }
    }
}

extern "C" void kernel_launch(void* const* d_in, const int* in_sizes, int n_in,
                              void* d_out, int out_size)
{
    const float* qkv = (const float*)d_in[0];
    float* out = (float*)d_out;
    (void)in_sizes; (void)n_in; (void)out_size;

    repack_kernel<<<1024, 128>>>(qkv);

    const int smem_bytes = SMEM_FLOATS * 4;   // 108544 B
    cudaFuncSetAttribute(attn_tf32_kernel,
                         cudaFuncAttributeMaxDynamicSharedMemorySize, smem_bytes);
    dim3 grid(SEQ / BQ, 64);   // 8 q-tiles x 64 heads = 512 CTAs
    attn_tf32_kernel<<<grid, 128, smem_bytes>>>(qkv, out);
}